// round 1
// baseline (speedup 1.0000x reference)
#include <cuda_runtime.h>

// QConv1d: quaternion conv via conjugation closed form.
// x: (B, CIN, T, 4)  [comp0=w, comp1=x, comp2=y, comp3=z]
// a,b,c: (COUT, CIN, FL)
// out: (B, COUT, TOUT, 4)

#define B_    2
#define CIN_  16
#define COUT_ 16
#define T_    2048
#define FL_   9
#define TOUT_ 2040

#define TILE_T    128
#define CI_GROUPS 2
#define CI_PER    (CIN_ / CI_GROUPS)

__global__ __launch_bounds__(TILE_T * CI_GROUPS)
void qconv1d_kernel(const float* __restrict__ x,
                    const float* __restrict__ pa,
                    const float* __restrict__ pb,
                    const float* __restrict__ pc,
                    float* __restrict__ out)
{
    const int t  = blockIdx.x * TILE_T + threadIdx.x;
    const int co = blockIdx.y;
    const int b  = blockIdx.z;
    const int g  = threadIdx.y;

    __shared__ float4 red[TILE_T];

    float aw = 0.f, ax = 0.f, ay = 0.f, az = 0.f;

    if (t < TOUT_) {
        const float4* xb = reinterpret_cast<const float4*>(x) + (size_t)b * CIN_ * T_;

        #pragma unroll 1
        for (int cig = 0; cig < CI_PER; ++cig) {
            const int ci = g * CI_PER + cig;
            const float4* xr = xb + (size_t)ci * T_ + t;

            // 9 taps in registers; tap f=4 is the "center" qp.
            float4 qv[FL_];
            #pragma unroll
            for (int f = 0; f < FL_; ++f) qv[f] = __ldg(xr + f);

            const float pw_ = qv[4].x;              // qp scalar part
            const float vx = qv[4].y, vy = qv[4].z, vz = qv[4].w;
            const float vsq = vx * vx + vy * vy + vz * vz;

            const float* pca = pc + (co * CIN_ + ci) * FL_;
            const float* pba = pb + (co * CIN_ + ci) * FL_;
            const float* paa = pa + (co * CIN_ + ci) * FL_;

            #pragma unroll
            for (int f = 0; f < FL_; ++f) {
                const float s  = qv[f].x;
                const float ux = qv[f].y, uy = qv[f].z, uz = qv[f].w;
                const float cv = __ldg(pca + f);
                const float bv = __ldg(pba + f);
                const float av = __ldg(paa + f);

                // p = qpc = (w, v), only scalar part shifted by c
                const float w   = pw_ + cv;
                const float d   = vx * ux + vy * uy + vz * uz;
                const float crx = vy * uz - vz * uy;
                const float cry = vz * ux - vx * uz;
                const float crz = vx * uy - vy * ux;
                const float wsq = w * w;
                const float nsq = wsq + vsq;
                const float dif = wsq - vsq;
                const float rn  = __fdividef(1.0f, nsq);
                const float d2 = d + d;
                const float w2 = w + w;

                // r = p q p^-1 : scalar preserved, vector rotated
                const float rw = s;
                const float rx = (dif * ux + d2 * vx + w2 * crx) * rn;
                const float ry = (dif * uy + d2 * vy + w2 * cry) * rn;
                const float rz = (dif * uz + d2 * vz + w2 * crz) * rn;

                // res2 = (q + b*e) (x) r
                const float qw2 = s + bv;
                const float ow = qw2 * rw - ux * rx - uy * ry - uz * rz;
                const float ox = qw2 * rx + ux * rw + uy * rz - uz * ry;
                const float oy = qw2 * ry - ux * rz + uy * rw + uz * rx;
                const float oz = qw2 * rz + ux * ry - uy * rx + uz * rw;

                aw = fmaf(av, ow, aw);
                ax = fmaf(av, ox, ax);
                ay = fmaf(av, oy, ay);
                az = fmaf(av, oz, az);
            }
        }
    }

    // reduce the two ci-groups
    if (g == 1) red[threadIdx.x] = make_float4(aw, ax, ay, az);
    __syncthreads();
    if (g == 0 && t < TOUT_) {
        const float4 r = red[threadIdx.x];
        float4 o;
        o.x = aw + r.x;
        o.y = ax + r.y;
        o.z = ay + r.z;
        o.w = az + r.w;
        reinterpret_cast<float4*>(out)[((size_t)b * COUT_ + co) * TOUT_ + t] = o;
    }
}

extern "C" void kernel_launch(void* const* d_in, const int* in_sizes, int n_in,
                              void* d_out, int out_size)
{
    const float* x  = (const float*)d_in[0];
    const float* pa = (const float*)d_in[1];
    const float* pb = (const float*)d_in[2];
    const float* pc = (const float*)d_in[3];
    float* out = (float*)d_out;

    dim3 block(TILE_T, CI_GROUPS, 1);
    dim3 grid((TOUT_ + TILE_T - 1) / TILE_T, COUT_, B_);
    qconv1d_kernel<<<grid, block>>>(x, pa, pb, pc, out);
}

// round 2
// speedup vs baseline: 1.0234x; 1.0234x over previous
#include <cuda_runtime.h>

// QConv1d: quaternion conv via conjugation closed form.
// x: (B, CIN, T, 4)  [comp0=w, comp1=x, comp2=y, comp3=z]
// a,b,c: (COUT, CIN, FL)
// out: (B, COUT, TOUT, 4)

#define B_    2
#define CIN_  16
#define COUT_ 16
#define T_    2048
#define FL_   9
#define TOUT_ 2040

#define TILE_T    128
#define CI_GROUPS 2
#define CI_PER    (CIN_ / CI_GROUPS)

__global__ __launch_bounds__(TILE_T * CI_GROUPS)
void qconv1d_kernel(const float* __restrict__ x,
                    const float* __restrict__ pa,
                    const float* __restrict__ pb,
                    const float* __restrict__ pc,
                    float* __restrict__ out)
{
    const int t  = blockIdx.x * TILE_T + threadIdx.x;
    const int co = blockIdx.y;
    const int b  = blockIdx.z;
    const int g  = threadIdx.y;

    __shared__ float4 red[TILE_T];

    float aw = 0.f, ax = 0.f, ay = 0.f, az = 0.f;

    if (t < TOUT_) {
        const float4* xb = reinterpret_cast<const float4*>(x) + (size_t)b * CIN_ * T_;

        #pragma unroll 1
        for (int cig = 0; cig < CI_PER; ++cig) {
            const int ci = g * CI_PER + cig;
            const float4* xr = xb + (size_t)ci * T_ + t;

            // 9 taps in registers; tap f=4 is the "center" qp.
            float4 qv[FL_];
            #pragma unroll
            for (int f = 0; f < FL_; ++f) qv[f] = __ldg(xr + f);

            const float pw_ = qv[4].x;              // qp scalar part
            const float vx = qv[4].y, vy = qv[4].z, vz = qv[4].w;
            const float vsq = vx * vx + vy * vy + vz * vz;

            const float* pca = pc + (co * CIN_ + ci) * FL_;
            const float* pba = pb + (co * CIN_ + ci) * FL_;
            const float* paa = pa + (co * CIN_ + ci) * FL_;

            #pragma unroll
            for (int f = 0; f < FL_; ++f) {
                const float s  = qv[f].x;
                const float ux = qv[f].y, uy = qv[f].z, uz = qv[f].w;
                const float cv = __ldg(pca + f);
                const float bv = __ldg(pba + f);
                const float av = __ldg(paa + f);

                // p = qpc = (w, v), only scalar part shifted by c
                const float w   = pw_ + cv;
                const float d   = vx * ux + vy * uy + vz * uz;
                const float crx = vy * uz - vz * uy;
                const float cry = vz * ux - vx * uz;
                const float crz = vx * uy - vy * ux;
                const float wsq = w * w;
                const float nsq = wsq + vsq;
                const float dif = wsq - vsq;
                const float rn  = __fdividef(1.0f, nsq);
                const float d2 = d + d;
                const float w2 = w + w;

                // r = p q p^-1 : scalar preserved, vector rotated
                const float rw = s;
                const float rx = (dif * ux + d2 * vx + w2 * crx) * rn;
                const float ry = (dif * uy + d2 * vy + w2 * cry) * rn;
                const float rz = (dif * uz + d2 * vz + w2 * crz) * rn;

                // res2 = (q + b*e) (x) r
                const float qw2 = s + bv;
                const float ow = qw2 * rw - ux * rx - uy * ry - uz * rz;
                const float ox = qw2 * rx + ux * rw + uy * rz - uz * ry;
                const float oy = qw2 * ry - ux * rz + uy * rw + uz * rx;
                const float oz = qw2 * rz + ux * ry - uy * rx + uz * rw;

                aw = fmaf(av, ow, aw);
                ax = fmaf(av, ox, ax);
                ay = fmaf(av, oy, ay);
                az = fmaf(av, oz, az);
            }
        }
    }

    // reduce the two ci-groups
    if (g == 1) red[threadIdx.x] = make_float4(aw, ax, ay, az);
    __syncthreads();
    if (g == 0 && t < TOUT_) {
        const float4 r = red[threadIdx.x];
        float4 o;
        o.x = aw + r.x;
        o.y = ax + r.y;
        o.z = ay + r.z;
        o.w = az + r.w;
        reinterpret_cast<float4*>(out)[((size_t)b * COUT_ + co) * TOUT_ + t] = o;
    }
}

extern "C" void kernel_launch(void* const* d_in, const int* in_sizes, int n_in,
                              void* d_out, int out_size)
{
    const float* x  = (const float*)d_in[0];
    const float* pa = (const float*)d_in[1];
    const float* pb = (const float*)d_in[2];
    const float* pc = (const float*)d_in[3];
    float* out = (float*)d_out;

    dim3 block(TILE_T, CI_GROUPS, 1);
    dim3 grid((TOUT_ + TILE_T - 1) / TILE_T, COUT_, B_);
    qconv1d_kernel<<<grid, block>>>(x, pa, pb, pc, out);
}

// round 3
// speedup vs baseline: 1.1677x; 1.1410x over previous
#include <cuda_runtime.h>

// QConv1d: quaternion conv via conjugation closed form.
// x: (B, CIN, T, 4)  [comp0=w, comp1=x, comp2=y, comp3=z]
// a,b,c: (COUT, CIN, FL)
// out: (B, COUT, TOUT, 4)

#define B_    2
#define CIN_  16
#define COUT_ 16
#define T_    2048
#define FL_   9
#define TOUT_ 2040

#define TILE_T    32
#define CI_GROUPS 8
#define CI_PER    (CIN_ / CI_GROUPS)

__global__ __launch_bounds__(TILE_T * CI_GROUPS)
void qconv1d_kernel(const float* __restrict__ x,
                    const float* __restrict__ pa,
                    const float* __restrict__ pb,
                    const float* __restrict__ pc,
                    float* __restrict__ out)
{
    const int t  = blockIdx.x * TILE_T + threadIdx.x;
    const int co = blockIdx.y;
    const int b  = blockIdx.z;
    const int g  = threadIdx.y;

    __shared__ float4 red[CI_GROUPS - 1][TILE_T];

    float aw = 0.f, ax = 0.f, ay = 0.f, az = 0.f;

    if (t < TOUT_) {
        const float4* xb = reinterpret_cast<const float4*>(x) + (size_t)b * CIN_ * T_;

        #pragma unroll
        for (int cig = 0; cig < CI_PER; ++cig) {
            const int ci = g * CI_PER + cig;
            const float4* xr = xb + (size_t)ci * T_ + t;

            // 9 taps in registers; tap f=4 is the "center" qp.
            float4 qv[FL_];
            #pragma unroll
            for (int f = 0; f < FL_; ++f) qv[f] = __ldg(xr + f);

            const float pw_ = qv[4].x;              // qp scalar part
            const float vx = qv[4].y, vy = qv[4].z, vz = qv[4].w;
            const float vsq = vx * vx + vy * vy + vz * vz;

            const float* pca = pc + (co * CIN_ + ci) * FL_;
            const float* pba = pb + (co * CIN_ + ci) * FL_;
            const float* paa = pa + (co * CIN_ + ci) * FL_;

            #pragma unroll
            for (int f = 0; f < FL_; ++f) {
                const float s  = qv[f].x;
                const float ux = qv[f].y, uy = qv[f].z, uz = qv[f].w;
                const float cv = __ldg(pca + f);
                const float bv = __ldg(pba + f);
                const float av = __ldg(paa + f);

                // p = qpc = (w, v), only scalar part shifted by c
                const float w   = pw_ + cv;
                const float d   = vx * ux + vy * uy + vz * uz;
                const float crx = vy * uz - vz * uy;
                const float cry = vz * ux - vx * uz;
                const float crz = vx * uy - vy * ux;
                const float wsq = w * w;
                const float nsq = wsq + vsq;
                const float dif = wsq - vsq;
                const float rn  = __fdividef(1.0f, nsq);
                const float d2  = d + d;
                const float w2  = w + w;

                // r = p q p^-1 : scalar preserved, vector rotated
                const float rw = s;
                const float rx = (dif * ux + d2 * vx + w2 * crx) * rn;
                const float ry = (dif * uy + d2 * vy + w2 * cry) * rn;
                const float rz = (dif * uz + d2 * vz + w2 * crz) * rn;

                // res2 = (q + b*e) (x) r
                const float qw2 = s + bv;
                const float ow = qw2 * rw - ux * rx - uy * ry - uz * rz;
                const float ox = qw2 * rx + ux * rw + uy * rz - uz * ry;
                const float oy = qw2 * ry - ux * rz + uy * rw + uz * rx;
                const float oz = qw2 * rz + ux * ry - uy * rx + uz * rw;

                aw = fmaf(av, ow, aw);
                ax = fmaf(av, ox, ax);
                ay = fmaf(av, oy, ay);
                az = fmaf(av, oz, az);
            }
        }
    }

    // reduce the 8 ci-groups
    if (g > 0) red[g - 1][threadIdx.x] = make_float4(aw, ax, ay, az);
    __syncthreads();
    if (g == 0 && t < TOUT_) {
        #pragma unroll
        for (int j = 0; j < CI_GROUPS - 1; ++j) {
            const float4 r = red[j][threadIdx.x];
            aw += r.x; ax += r.y; ay += r.z; az += r.w;
        }
        float4 o = make_float4(aw, ax, ay, az);
        reinterpret_cast<float4*>(out)[((size_t)b * COUT_ + co) * TOUT_ + t] = o;
    }
}

extern "C" void kernel_launch(void* const* d_in, const int* in_sizes, int n_in,
                              void* d_out, int out_size)
{
    const float* x  = (const float*)d_in[0];
    const float* pa = (const float*)d_in[1];
    const float* pb = (const float*)d_in[2];
    const float* pc = (const float*)d_in[3];
    float* out = (float*)d_out;

    dim3 block(TILE_T, CI_GROUPS, 1);
    dim3 grid((TOUT_ + TILE_T - 1) / TILE_T, COUT_, B_);
    qconv1d_kernel<<<grid, block>>>(x, pa, pb, pc, out);
}